// round 12
// baseline (speedup 1.0000x reference)
#include <cuda_runtime.h>
#include <math_constants.h>

#define H 1024
#define V 50257
#define L 12
#define TILES ((V + 7) / 8)          // 6283 blocks in k3, 8 rows each

// ---- device scratch (no allocations allowed), 16B-aligned ----
__device__ __align__(16) float g_x[H];         // relu(combine) output
__device__ __align__(16) float g_h[H];         // h_new (aligned copy)
__device__ __align__(16) float g_hh[4 * H];    // W_hh@h0 + b_ih + b_hh
__device__ float g_sum;                        // global sum(exp(logit)) accumulator

__device__ __forceinline__ float warp_sum(float v) {
#pragma unroll
    for (int o = 16; o; o >>= 1) v += __shfl_xor_sync(0xffffffffu, v, o);
    return v;
}

__device__ __forceinline__ float4 ldcs4(const float4* p) { return __ldcs(p); }

__device__ __forceinline__ void pdl_wait() {
#if __CUDA_ARCH__ >= 900
    cudaGridDependencySynchronize();
#endif
}

// ============================================================
// Kernel 1:
//   blocks 0..127   : attention + combine (8 rows each)
//   blocks 128..639 : hh gate half: g_hh[r] = W_hh[r]@h0 + b_ih[r] + b_hh[r]
// Block 0 also resets g_sum for this graph replay (runs before k3).
// ============================================================
__global__ void k1_attn_comb_hh(const int* input,
                                const float* __restrict__ h_hidden,
                                const float* __restrict__ enc,
                                const float* __restrict__ emb,
                                const float* __restrict__ attn_W,
                                const float* __restrict__ attn_b,
                                const float* __restrict__ comb_W,
                                const float* __restrict__ comb_b,
                                const float* __restrict__ W_hh,
                                const float* __restrict__ b_ih,
                                const float* __restrict__ b_hh,
                                float* __restrict__ attnw_out) {
    const int tid = threadIdx.x;
    const int w = tid >> 5, lane = tid & 31;

    if (blockIdx.x >= 128) {
        __shared__ __align__(16) float4 s_h[256];
        s_h[tid] = ((const float4*)h_hidden)[tid];
        __syncthreads();
        const int r = (blockIdx.x - 128) * 8 + w;      // [0, 4096)
        const float4* row = (const float4*)(W_hh + (size_t)r * H);
        float acc = 0.f;
#pragma unroll
        for (int t = 0; t < 8; t++) {
            float4 a = ldcs4(row + lane + 32 * t);
            float4 b = s_h[lane + 32 * t];
            acc += a.x * b.x + a.y * b.y + a.z * b.z + a.w * b.w;
        }
        acc = warp_sum(acc);
        if (lane == 0) g_hh[r] = acc + b_ih[r] + b_hh[r];
        return;
    }

    __shared__ __align__(16) float s_in[2 * H];   // [emb ; h0]
    __shared__ __align__(16) float s_cx[2 * H];   // [emb ; applied]
    __shared__ float s_logit[L];
    __shared__ float s_w[L];

    if (blockIdx.x == 0 && tid == 0) g_sum = 0.f;  // reset accumulator per replay

    const int idx = input[0];     // low 32 bits of LE int64 index
    const float* e = emb + (size_t)idx * H;
    for (int i = tid; i < H; i += 256) {
        float v = e[i];
        s_in[i] = v;
        s_cx[i] = v;
        s_in[H + i] = h_hidden[i];
    }
    __syncthreads();

    const float4* s_in4 = (const float4*)s_in;
    for (int l = w; l < L; l += 8) {
        const float4* row = (const float4*)(attn_W + (size_t)l * 2 * H);
        float acc = 0.f;
#pragma unroll
        for (int t = 0; t < 16; t++) {
            float4 a = row[lane + 32 * t];
            float4 b = s_in4[lane + 32 * t];
            acc += a.x * b.x + a.y * b.y + a.z * b.z + a.w * b.w;
        }
        acc = warp_sum(acc);
        if (lane == 0) s_logit[l] = acc + attn_b[l];
    }
    __syncthreads();

    if (tid == 0) {
        float m = -1e30f;
#pragma unroll
        for (int l = 0; l < L; l++) m = fmaxf(m, s_logit[l]);
        float s = 0.f;
#pragma unroll
        for (int l = 0; l < L; l++) { float ex = expf(s_logit[l] - m); s_w[l] = ex; s += ex; }
        float inv = 1.f / s;
#pragma unroll
        for (int l = 0; l < L; l++) s_w[l] *= inv;
        if (blockIdx.x == 0)
#pragma unroll
            for (int l = 0; l < L; l++) attnw_out[l] = s_w[l];
    }
    __syncthreads();

    for (int j = tid; j < H; j += 256) {
        float acc = 0.f;
#pragma unroll
        for (int l = 0; l < L; l++) acc += s_w[l] * enc[l * H + j];
        s_cx[H + j] = acc;
    }
    __syncthreads();

    const int r = blockIdx.x * 8 + w;
    const float4* s_cx4 = (const float4*)s_cx;
    const float4* row = (const float4*)(comb_W + (size_t)r * 2 * H);
    float acc = 0.f;
#pragma unroll
    for (int t = 0; t < 16; t++) {
        float4 a = ldcs4(row + lane + 32 * t);
        float4 b = s_cx4[lane + 32 * t];
        acc += a.x * b.x + a.y * b.y + a.z * b.z + a.w * b.w;
    }
    acc = warp_sum(acc);
    if (lane == 0) g_x[r] = fmaxf(acc + comb_b[r], 0.f);
}

// ============================================================
// Kernel 2: ih-half of gates + LSTM cell, fused. PDL consumer.
// One warp per hidden unit j (4 W_ih rows, processed pairwise).
// ============================================================
__global__ void k2_gates_cell(const float* __restrict__ c_hidden,
                              const float* __restrict__ W_ih,
                              float* __restrict__ h_new,
                              float* __restrict__ c_new) {
    __shared__ __align__(16) float4 s_x[256];
    const int tid = threadIdx.x;
    pdl_wait();                         // wait for k1's g_x / g_hh
    s_x[tid] = ((const float4*)g_x)[tid];
    __syncthreads();

    const int w = tid >> 5, lane = tid & 31;
    const int j = blockIdx.x * 8 + w;

    float gate[4];
#pragma unroll
    for (int gp = 0; gp < 2; gp++) {
        const float4* r0 = (const float4*)(W_ih + (size_t)((2 * gp) * H + j) * H);
        const float4* r1 = (const float4*)(W_ih + (size_t)((2 * gp + 1) * H + j) * H);
        float a0 = 0.f, a1 = 0.f;
#pragma unroll
        for (int t = 0; t < 8; t++) {
            float4 w0 = ldcs4(r0 + lane + 32 * t);
            float4 w1 = ldcs4(r1 + lane + 32 * t);
            float4 xb = s_x[lane + 32 * t];
            a0 += w0.x * xb.x + w0.y * xb.y + w0.z * xb.z + w0.w * xb.w;
            a1 += w1.x * xb.x + w1.y * xb.y + w1.z * xb.z + w1.w * xb.w;
        }
        gate[2 * gp]     = warp_sum(a0);
        gate[2 * gp + 1] = warp_sum(a1);
    }
    if (lane == 0) {
        float gi = gate[0] + g_hh[j];
        float gf = gate[1] + g_hh[H + j];
        float gg = gate[2] + g_hh[2 * H + j];
        float go = gate[3] + g_hh[3 * H + j];
        float si = 1.f / (1.f + expf(-gi));
        float sf = 1.f / (1.f + expf(-gf));
        float so = 1.f / (1.f + expf(-go));
        float c = sf * c_hidden[j] + si * tanhf(gg);
        float h = so * tanhf(c);
        c_new[j] = c;
        h_new[j] = h;
        g_h[j] = h;
    }
}

// ============================================================
// Kernel 3: output projection (50257 x 1024), 8 rows/block,
// one warp per row. PDL consumer. Per-block sum(exp) partial via
// fire-and-forget atomicAdd (REDG) — no fence, no drain.
// ============================================================
__global__ void k3_out(const float* __restrict__ out_W,
                       const float* __restrict__ out_b,
                       float* __restrict__ logits) {
    __shared__ __align__(16) float4 s_h[256];
    __shared__ float s_l[8];
    const int tid = threadIdx.x;
    pdl_wait();                         // wait for k2's g_h
    s_h[tid] = ((const float4*)g_h)[tid];
    __syncthreads();

    const int w = tid >> 5, lane = tid & 31;
    const int r = blockIdx.x * 8 + w;
    float l = -CUDART_INF_F;
    if (r < V) {
        const float4* row = (const float4*)(out_W + (size_t)r * H);
        float acc = 0.f;
#pragma unroll
        for (int t = 0; t < 8; t++) {
            float4 a = ldcs4(row + lane + 32 * t);
            float4 b = s_h[lane + 32 * t];
            acc += a.x * b.x + a.y * b.y + a.z * b.z + a.w * b.w;
        }
        acc = warp_sum(acc);
        if (lane == 0) {
            l = acc + out_b[r];
            logits[r] = l;
        }
    }
    if (lane == 0) s_l[w] = l;
    __syncthreads();
    if (tid == 0) {
        float s = 0.f;
#pragma unroll
        for (int i = 0; i < 8; i++) {
            float v = s_l[i];
            if (v != -CUDART_INF_F) s += expf(v);
        }
        atomicAdd(&g_sum, s);          // REDG: no return value, no fence
    }
}

// ============================================================
// Kernel 4: logp[i] = logits[i] - log(g_sum). PDL consumer.
// ============================================================
__global__ void k4_sub(float* __restrict__ logp) {
    __shared__ float s_lse;
    const int tid = threadIdx.x;
    pdl_wait();                         // wait for k3's logits / g_sum
    if (tid == 0) s_lse = logf(g_sum);
    __syncthreads();
    const float lse = s_lse;
    const int i = blockIdx.x * 256 + tid;
    if (i < V) logp[i] -= lse;
}

// ============================================================
static inline void launch_pdl(void* fn, dim3 grid, dim3 block,
                              void** args) {
    cudaLaunchAttribute attr[1];
    attr[0].id = cudaLaunchAttributeProgrammaticStreamSerialization;
    attr[0].val.programmaticStreamSerializationAllowed = 1;
    cudaLaunchConfig_t cfg = {};
    cfg.gridDim = grid;
    cfg.blockDim = block;
    cfg.dynamicSmemBytes = 0;
    cfg.stream = 0;
    cfg.attrs = attr;
    cfg.numAttrs = 1;
    cudaLaunchKernelExC(&cfg, fn, args);
}

extern "C" void kernel_launch(void* const* d_in, const int* in_sizes, int n_in,
                              void* d_out, int out_size) {
    const int*   input   = (const int*)  d_in[0];
    const float* h_hid   = (const float*)d_in[1];
    const float* c_hid   = (const float*)d_in[2];
    const float* enc     = (const float*)d_in[3];
    const float* emb     = (const float*)d_in[4];
    const float* attn_W  = (const float*)d_in[5];
    const float* attn_b  = (const float*)d_in[6];
    const float* comb_W  = (const float*)d_in[7];
    const float* comb_b  = (const float*)d_in[8];
    const float* W_ih    = (const float*)d_in[9];
    const float* W_hh    = (const float*)d_in[10];
    const float* b_ih    = (const float*)d_in[11];
    const float* b_hh    = (const float*)d_in[12];
    const float* out_W   = (const float*)d_in[13];
    const float* out_b   = (const float*)d_in[14];

    float* out   = (float*)d_out;
    float* logp  = out;                 // [V]
    float* h_new = out + V;             // [H]
    float* c_new = out + V + H;         // [H]
    float* attnw = out + V + 2 * H;     // [L]

    k1_attn_comb_hh<<<128 + 512, 256>>>(input, h_hid, enc, emb, attn_W, attn_b,
                                        comb_W, comb_b, W_hh, b_ih, b_hh, attnw);

    {   // k2 with PDL
        void* args[] = { (void*)&c_hid, (void*)&W_ih, (void*)&h_new, (void*)&c_new };
        launch_pdl((void*)k2_gates_cell, dim3(128), dim3(256), args);
    }
    {   // k3 with PDL
        void* args[] = { (void*)&out_W, (void*)&out_b, (void*)&logp };
        launch_pdl((void*)k3_out, dim3(TILES), dim3(256), args);
    }
    {   // k4 with PDL
        void* args[] = { (void*)&logp };
        launch_pdl((void*)k4_sub, dim3((V + 255) / 256), dim3(256), args);
    }
}